// round 1
// baseline (speedup 1.0000x reference)
#include <cuda_runtime.h>

// Problem constants
#define Bb 2
#define Ss 2048
#define Ee 1024
#define Hh 16
#define Dd 64
#define SCALE (1.0f/32.0f)   // 1/sqrt(E)

// ---------------------------------------------------------------------------
// Scratch (device globals; allocation inside kernel_launch is forbidden)
// ---------------------------------------------------------------------------
__device__ float g_q  [(size_t)Bb*Hh*Ss*Dd];   // [b,h,s,d]
__device__ float g_kT [(size_t)Bb*Hh*Dd*Ss];   // [b,h,d,s]  (transposed K!)
__device__ float g_v  [(size_t)Bb*Hh*Ss*Dd];   // [b,h,s,d]
__device__ float g_sk [(size_t)Bb*Hh*Ss];      // 0.5*SCALE*||k||^2 per (b,h,s)
__device__ float g_att[(size_t)Bb*Ss*Ee];      // attention output, concat layout [b,s,e]

// ---------------------------------------------------------------------------
// Kernel 1: fused QKV projection.  out[b,h,s,d] = sum_e X[b,s,e]*W[h,e,d] + bias[h,d]
// GEMM: [4096,1024] x [1024,1024] per z in {Q,K,V}.  128x128x16 tiles, 8x8 micro.
// z==1 (K) writes its output transposed to g_kT[b,h,d,s].
// ---------------------------------------------------------------------------
__global__ __launch_bounds__(256) void proj_kernel(
    const float* __restrict__ Xq, const float* __restrict__ Xk, const float* __restrict__ Xv,
    const float* __restrict__ Wq, const float* __restrict__ Wk, const float* __restrict__ Wv,
    const float* __restrict__ Bq, const float* __restrict__ Bk, const float* __restrict__ Bv)
{
    const int z = blockIdx.z;
    const float* X    = (z==0) ? Xq : ((z==1) ? Xk : Xv);
    const float* W    = (z==0) ? Wq : ((z==1) ? Wk : Wv);
    const float* bias = (z==0) ? Bq : ((z==1) ? Bk : Bv);

    __shared__ float Xs[16][132];   // transposed X tile: Xs[k][m], padded pitch
    __shared__ float Ws[16][128];   // Ws[k][n]

    const int tid = threadIdx.x;
    const int tx = tid & 15, ty = tid >> 4;
    const int m0 = blockIdx.x * 128;
    const int n0 = blockIdx.y * 128;

    float acc[8][8];
    #pragma unroll
    for (int i = 0; i < 8; i++)
        #pragma unroll
        for (int j = 0; j < 8; j++) acc[i][j] = 0.f;

    for (int k0 = 0; k0 < Ee; k0 += 16) {
        // Load X tile [128 m x 16 k], store transposed into Xs[k][m]
        #pragma unroll
        for (int u = 0; u < 2; u++) {
            int idx = tid + u * 256;          // 0..511
            int r   = idx >> 2;               // 0..127  (m within tile)
            int kc  = (idx & 3) << 2;         // 0,4,8,12
            float4 xv = *(const float4*)(X + (size_t)(m0 + r) * Ee + k0 + kc);
            Xs[kc+0][r] = xv.x; Xs[kc+1][r] = xv.y;
            Xs[kc+2][r] = xv.z; Xs[kc+3][r] = xv.w;
        }
        // Load W tile [16 k x 128 n]; col n -> (h=n>>6, d=n&63), W[h*E*D + e*D + d]
        #pragma unroll
        for (int u = 0; u < 2; u++) {
            int idx = tid + u * 256;
            int kk  = idx >> 5;               // 0..15
            int nc  = (idx & 31) << 2;        // 0..124
            int n = n0 + nc;
            int h = n >> 6, d = n & 63;
            *(float4*)&Ws[kk][nc] =
                *(const float4*)(W + (size_t)h * (Ee*Dd) + (size_t)(k0 + kk) * Dd + d);
        }
        __syncthreads();

        #pragma unroll
        for (int kk = 0; kk < 16; kk++) {
            float a[8], b[8];
            *(float4*)&a[0] = *(float4*)&Xs[kk][ty*4];
            *(float4*)&a[4] = *(float4*)&Xs[kk][64 + ty*4];
            *(float4*)&b[0] = *(float4*)&Ws[kk][tx*4];
            *(float4*)&b[4] = *(float4*)&Ws[kk][64 + tx*4];
            #pragma unroll
            for (int i = 0; i < 8; i++)
                #pragma unroll
                for (int j = 0; j < 8; j++)
                    acc[i][j] = fmaf(a[i], b[j], acc[i][j]);
        }
        __syncthreads();
    }

    // Epilogue: add bias, scatter to [b,h,s,d] (or transposed for K)
    #pragma unroll
    for (int ii = 0; ii < 2; ii++)
        #pragma unroll
        for (int i2 = 0; i2 < 4; i2++) {
            int i = ii*4 + i2;
            int m = m0 + ii*64 + ty*4 + i2;
            int bb = m >> 11, s = m & 2047;
            #pragma unroll
            for (int jj = 0; jj < 2; jj++)
                #pragma unroll
                for (int j2 = 0; j2 < 4; j2++) {
                    int j = jj*4 + j2;
                    int n = n0 + jj*64 + tx*4 + j2;
                    int h = n >> 6, d = n & 63;
                    float val = acc[i][j] + bias[h*Dd + d];
                    if (z == 1) {
                        g_kT[(((size_t)bb*Hh + h)*Dd + d)*Ss + s] = val;
                    } else {
                        float* out = (z == 0) ? g_q : g_v;
                        out[(((size_t)bb*Hh + h)*Ss + s)*Dd + d] = val;
                    }
                }
        }
}

// ---------------------------------------------------------------------------
// Kernel 2: g_sk[b,h,s] = 0.5*SCALE*||k[b,h,s,:]||^2  (reads transposed K,
// coalesced: lane index = s)
// ---------------------------------------------------------------------------
__global__ __launch_bounds__(256) void knorm_kernel()
{
    int idx = blockIdx.x * 256 + threadIdx.x;   // 0..65535 = [bh][s]
    int bh = idx >> 11;
    int s  = idx & 2047;
    const float* kp = g_kT + (size_t)bh * Dd * Ss + s;
    float acc = 0.f;
    #pragma unroll
    for (int d = 0; d < Dd; d++) {
        float v = kp[(size_t)d * Ss];
        acc = fmaf(v, v, acc);
    }
    g_sk[idx] = 0.5f * SCALE * acc;
}

// ---------------------------------------------------------------------------
// Kernel 3: flash attention per (b,h).  Online softmax over key tiles.
// scores = q.k*SCALE - 0.5*||k||^2*SCALE   (the -0.5||q||^2 term cancels in
// softmax and is dropped).  BQ=64 x BKEY=64 tiles, 4x4 micro-tiles, 256 thr.
// K tile comes in pre-transposed [d][key]; P reuses the K smem buffer.
// All smem accesses are broadcast or contiguous -> no padding, 48KB exactly.
// ---------------------------------------------------------------------------
__global__ __launch_bounds__(256) void flash_kernel()
{
    __shared__ float Qs [64*64];   // Qs[row][d]
    __shared__ float KPs[64*64];   // K phase: KPs[d][key]; P phase: KPs[row][key]
    __shared__ float Vs [64*64];   // Vs[key][dv]

    const int bh = blockIdx.y;            // 0..31  (b*16+h)
    const int q0 = blockIdx.x * 64;
    const float* Qg  = g_q  + (size_t)bh * Ss * Dd + (size_t)q0 * Dd;
    const float* KTg = g_kT + (size_t)bh * Dd * Ss;
    const float* Vg  = g_v  + (size_t)bh * Ss * Dd;
    const float* skg = g_sk + (size_t)bh * Ss;

    const int tid = threadIdx.x;
    const int tx = tid & 15, ty = tid >> 4;

    // Load Q tile [64][64]
    #pragma unroll
    for (int u = 0; u < 4; u++) {
        int idx = tid + u * 256;
        int r = idx >> 4, c = (idx & 15) << 2;
        *(float4*)&Qs[r*64 + c] = *(const float4*)(Qg + (size_t)r * Dd + c);
    }

    float m_i[4], l_i[4], acc[4][4];
    #pragma unroll
    for (int i = 0; i < 4; i++) {
        m_i[i] = -3.0e38f; l_i[i] = 0.f;
        #pragma unroll
        for (int j = 0; j < 4; j++) acc[i][j] = 0.f;
    }

    for (int k0 = 0; k0 < Ss; k0 += 64) {
        __syncthreads();   // previous-iteration KPs/Vs readers done (also covers Qs on iter 0)
        // Load K (transposed layout [d][key]) and V ([key][dv])
        #pragma unroll
        for (int u = 0; u < 4; u++) {
            int idx = tid + u * 256;
            int r = idx >> 4, c = (idx & 15) << 2;
            *(float4*)&KPs[r*64 + c] = *(const float4*)(KTg + (size_t)r * Ss + k0 + c);
            *(float4*)&Vs [r*64 + c] = *(const float4*)(Vg  + (size_t)(k0 + r) * Dd + c);
        }
        __syncthreads();

        // ---- scores: sc[i][j] = sum_d Q[row_i][d] * K[key_j][d] ----
        float sc[4][4];
        #pragma unroll
        for (int i = 0; i < 4; i++)
            #pragma unroll
            for (int j = 0; j < 4; j++) sc[i][j] = 0.f;

        for (int d0 = 0; d0 < 64; d0 += 4) {
            float qa[4][4], kb[4][4];
            #pragma unroll
            for (int i = 0; i < 4; i++)
                *(float4*)qa[i] = *(const float4*)&Qs[(ty*4 + i)*64 + d0];
            #pragma unroll
            for (int dd = 0; dd < 4; dd++)
                *(float4*)kb[dd] = *(const float4*)&KPs[(d0 + dd)*64 + tx*4];
            #pragma unroll
            for (int i = 0; i < 4; i++)
                #pragma unroll
                for (int dd = 0; dd < 4; dd++)
                    #pragma unroll
                    for (int j = 0; j < 4; j++)
                        sc[i][j] = fmaf(qa[i][dd], kb[dd][j], sc[i][j]);
        }

        // ---- online softmax update ----
        float skv[4];
        #pragma unroll
        for (int j = 0; j < 4; j++) skv[j] = skg[k0 + tx*4 + j];

        #pragma unroll
        for (int i = 0; i < 4; i++) {
            float mx = -3.0e38f;
            #pragma unroll
            for (int j = 0; j < 4; j++) {
                sc[i][j] = fmaf(sc[i][j], SCALE, -skv[j]);
                mx = fmaxf(mx, sc[i][j]);
            }
            #pragma unroll
            for (int o = 8; o >= 1; o >>= 1)
                mx = fmaxf(mx, __shfl_xor_sync(0xffffffffu, mx, o));   // within 16-lane row group
            float mn = fmaxf(m_i[i], mx);
            float al = __expf(m_i[i] - mn);
            m_i[i] = mn;
            float ps = 0.f;
            #pragma unroll
            for (int j = 0; j < 4; j++) {
                sc[i][j] = __expf(sc[i][j] - mn);
                ps += sc[i][j];
            }
            #pragma unroll
            for (int o = 8; o >= 1; o >>= 1)
                ps += __shfl_xor_sync(0xffffffffu, ps, o);
            l_i[i] = l_i[i] * al + ps;
            #pragma unroll
            for (int j = 0; j < 4; j++) acc[i][j] *= al;
        }

        __syncthreads();   // everyone finished reading K from KPs
        // write P into KPs: P[row][key]
        #pragma unroll
        for (int i = 0; i < 4; i++) {
            float4 pv = make_float4(sc[i][0], sc[i][1], sc[i][2], sc[i][3]);
            *(float4*)&KPs[(ty*4 + i)*64 + tx*4] = pv;
        }
        __syncthreads();

        // ---- PV: acc[i][j] += sum_key P[row_i][key] * V[key][dv_j] ----
        for (int kk0 = 0; kk0 < 64; kk0 += 4) {
            float pa[4][4], vb[4][4];
            #pragma unroll
            for (int i = 0; i < 4; i++)
                *(float4*)pa[i] = *(const float4*)&KPs[(ty*4 + i)*64 + kk0];
            #pragma unroll
            for (int kk = 0; kk < 4; kk++)
                *(float4*)vb[kk] = *(const float4*)&Vs[(kk0 + kk)*64 + tx*4];
            #pragma unroll
            for (int i = 0; i < 4; i++)
                #pragma unroll
                for (int kk = 0; kk < 4; kk++)
                    #pragma unroll
                    for (int j = 0; j < 4; j++)
                        acc[i][j] = fmaf(pa[i][kk], vb[kk][j], acc[i][j]);
        }
    }

    // Epilogue: normalize and write concat layout g_att[b, s, h*64 + dv]
    const int b = bh >> 4, h = bh & 15;
    #pragma unroll
    for (int i = 0; i < 4; i++) {
        int s = q0 + ty*4 + i;
        float inv = 1.0f / l_i[i];
        float4 ov = make_float4(acc[i][0]*inv, acc[i][1]*inv, acc[i][2]*inv, acc[i][3]*inv);
        *(float4*)&g_att[((size_t)b*Ss + s)*Ee + h*Dd + tx*4] = ov;
    }
}

// ---------------------------------------------------------------------------
// Kernel 4: residual add + custom LayerNorm.
// x = att + residual;  out = scale*(x-mean)/(std_ddof1 + eps + shift)
// One block (256 thr) per row of 1024 features.
// ---------------------------------------------------------------------------
__global__ __launch_bounds__(256) void ln_kernel(
    const float* __restrict__ resid, const float* __restrict__ gamma,
    const float* __restrict__ beta, float* __restrict__ out)
{
    const int row = blockIdx.x;            // 0..4095
    const float* xa = g_att + (size_t)row * Ee;
    const float* xr = resid + (size_t)row * Ee;
    const int tid = threadIdx.x;

    float4 a = *(const float4*)(xa + tid*4);
    float4 r = *(const float4*)(xr + tid*4);
    float x0 = a.x + r.x, x1 = a.y + r.y, x2 = a.z + r.z, x3 = a.w + r.w;

    float sum = x0 + x1 + x2 + x3;
    float sq  = x0*x0 + x1*x1 + x2*x2 + x3*x3;
    #pragma unroll
    for (int o = 16; o >= 1; o >>= 1) {
        sum += __shfl_xor_sync(0xffffffffu, sum, o);
        sq  += __shfl_xor_sync(0xffffffffu, sq,  o);
    }
    __shared__ float rs[8], rq[8];
    int w = tid >> 5, lane = tid & 31;
    if (lane == 0) { rs[w] = sum; rq[w] = sq; }
    __syncthreads();
    float ts = 0.f, tq = 0.f;
    #pragma unroll
    for (int i = 0; i < 8; i++) { ts += rs[i]; tq += rq[i]; }

    float mean = ts * (1.0f/1024.0f);
    float var  = (tq - 1024.0f * mean * mean) * (1.0f/1023.0f);  // ddof=1
    float stdv = sqrtf(var);

    float4 gv = *(const float4*)(gamma + tid*4);
    float4 bv = *(const float4*)(beta  + tid*4);
    float4 o4;
    o4.x = gv.x * (x0 - mean) / (stdv + 1e-6f + bv.x);
    o4.y = gv.y * (x1 - mean) / (stdv + 1e-6f + bv.y);
    o4.z = gv.z * (x2 - mean) / (stdv + 1e-6f + bv.z);
    o4.w = gv.w * (x3 - mean) / (stdv + 1e-6f + bv.w);
    *(float4*)(out + (size_t)row * Ee + tid*4) = o4;
}

// ---------------------------------------------------------------------------
// Launch.  Inputs (metadata order): query, key, value, residual_x,
// Wq, bq, Wk, bk, Wv, bv, scale, shift.  Output: float32 [2,2048,1024].
// ---------------------------------------------------------------------------
extern "C" void kernel_launch(void* const* d_in, const int* in_sizes, int n_in,
                              void* d_out, int out_size)
{
    (void)in_sizes; (void)n_in; (void)out_size;
    const float* query = (const float*)d_in[0];
    const float* key   = (const float*)d_in[1];
    const float* value = (const float*)d_in[2];
    const float* resid = (const float*)d_in[3];
    const float* Wq = (const float*)d_in[4];
    const float* bq = (const float*)d_in[5];
    const float* Wk = (const float*)d_in[6];
    const float* bk = (const float*)d_in[7];
    const float* Wv = (const float*)d_in[8];
    const float* bv = (const float*)d_in[9];
    const float* gamma = (const float*)d_in[10];
    const float* beta  = (const float*)d_in[11];
    float* out = (float*)d_out;

    dim3 gproj(32, 8, 3);                  // 4096/128 m-tiles, 1024/128 n-tiles, {Q,K,V}
    proj_kernel<<<gproj, 256>>>(query, key, value, Wq, Wk, Wv, bq, bk, bv);
    knorm_kernel<<<256, 256>>>();          // 65536 rows
    flash_kernel<<<dim3(32, 32), 256>>>(); // 32 q-tiles x 32 (b,h)
    ln_kernel<<<4096, 256>>>(resid, gamma, beta, out);
}

// round 2
// speedup vs baseline: 2.3684x; 2.3684x over previous
#include <cuda_runtime.h>

// Problem constants
#define Bb 2
#define Ss 2048
#define Ee 1024
#define Hh 16
#define Dd 64
#define SCALE (1.0f/32.0f)   // 1/sqrt(E)

// ---------------------------------------------------------------------------
// Scratch (device globals; allocation inside kernel_launch is forbidden)
// ---------------------------------------------------------------------------
__device__ float g_q  [(size_t)Bb*Hh*Ss*Dd];   // [b,h,s,d]
__device__ float g_kT [(size_t)Bb*Hh*Dd*Ss];   // [b,h,d,s]  (transposed K)
__device__ float g_v  [(size_t)Bb*Hh*Ss*Dd];   // [b,h,s,d]
__device__ float g_sk [(size_t)Bb*Hh*Ss];      // 0.5*SCALE*||k||^2 per (b,h,s)
__device__ float g_att[(size_t)Bb*Ss*Ee];      // attention output, concat layout [b,s,e]

// ---------------------------------------------------------------------------
// TF32 helpers
// ---------------------------------------------------------------------------
__device__ __forceinline__ unsigned f2tf(float x) {
    unsigned r; asm("cvt.rna.tf32.f32 %0, %1;" : "=r"(r) : "f"(x)); return r;
}
__device__ __forceinline__ void mma_tf32(float* c, const unsigned* a, const unsigned* b) {
    asm volatile(
        "mma.sync.aligned.m16n8k8.row.col.f32.tf32.tf32.f32 "
        "{%0,%1,%2,%3}, {%4,%5,%6,%7}, {%8,%9}, {%0,%1,%2,%3};"
        : "+f"(c[0]), "+f"(c[1]), "+f"(c[2]), "+f"(c[3])
        : "r"(a[0]), "r"(a[1]), "r"(a[2]), "r"(a[3]), "r"(b[0]), "r"(b[1]));
}

// ---------------------------------------------------------------------------
// Kernel 1: fused QKV projection via tf32 mma.
// out[b,h,s,d] = sum_e X[b,s,e]*W[h,e,d] + bias[h,d]
// GEMM [4096,1024]x[1024,1024] per z.  Block tile 128x128, K-chunk 32.
// 8 warps: warp tile 64(M)x32(N) = 4x4 m16n8k8 tiles.
// Xs stored [m][k] pitch 36 (A-frag loads conflict-free: bank=4g+qd).
// Ws stored [k][n] pitch 132 (B-frag loads conflict-free: bank=4qd+g).
// z==1 (K) writes output transposed to g_kT[b,h,d,s].
// ---------------------------------------------------------------------------
__global__ __launch_bounds__(256) void proj_kernel(
    const float* __restrict__ Xq, const float* __restrict__ Xk, const float* __restrict__ Xv,
    const float* __restrict__ Wq, const float* __restrict__ Wk, const float* __restrict__ Wv,
    const float* __restrict__ Bq, const float* __restrict__ Bk, const float* __restrict__ Bv)
{
    const int z = blockIdx.z;
    const float* X    = (z==0) ? Xq : ((z==1) ? Xk : Xv);
    const float* W    = (z==0) ? Wq : ((z==1) ? Wk : Wv);
    const float* bias = (z==0) ? Bq : ((z==1) ? Bk : Bv);

    __shared__ unsigned Xs[128][36];   // [m][k], pitch 36
    __shared__ unsigned Ws[32][132];   // [k][n], pitch 132

    const int tid  = threadIdx.x;
    const int wid  = tid >> 5, lane = tid & 31;
    const int g    = lane >> 2, qd = lane & 3;
    const int wm   = (wid & 1) * 64;       // warp M offset in block tile
    const int wn   = (wid >> 1) * 32;      // warp N offset
    const int m0   = blockIdx.x * 128;
    const int n0   = blockIdx.y * 128;

    float acc[4][4][4];
    #pragma unroll
    for (int mi = 0; mi < 4; mi++)
        #pragma unroll
        for (int nj = 0; nj < 4; nj++)
            #pragma unroll
            for (int r = 0; r < 4; r++) acc[mi][nj][r] = 0.f;

    for (int k0 = 0; k0 < Ee; k0 += 32) {
        // Load X tile [128 m][32 k]: 1024 float4 / 256 thr = 4 each
        #pragma unroll
        for (int u = 0; u < 4; u++) {
            int idx = u * 256 + tid;
            int r = idx >> 3, c4 = (idx & 7) << 2;
            float4 xv = *(const float4*)(X + (size_t)(m0 + r) * Ee + k0 + c4);
            uint4 t = make_uint4(f2tf(xv.x), f2tf(xv.y), f2tf(xv.z), f2tf(xv.w));
            *(uint4*)&Xs[r][c4] = t;
        }
        // Load W tile [32 k][128 n]; n -> (h=n>>6, d=n&63)
        #pragma unroll
        for (int u = 0; u < 4; u++) {
            int idx = u * 256 + tid;
            int kk = idx >> 5, c4 = (idx & 31) << 2;
            int n = n0 + c4;
            int h = n >> 6, d = n & 63;
            float4 wv = *(const float4*)(W + (size_t)h * (Ee*Dd) + (size_t)(k0 + kk) * Dd + d);
            uint4 t = make_uint4(f2tf(wv.x), f2tf(wv.y), f2tf(wv.z), f2tf(wv.w));
            *(uint4*)&Ws[kk][c4] = t;
        }
        __syncthreads();

        #pragma unroll
        for (int ks = 0; ks < 4; ks++) {
            unsigned a[4][4], b[4][2];
            #pragma unroll
            for (int mi = 0; mi < 4; mi++) {
                int row = wm + mi*16 + g;
                int col = ks*8 + qd;
                a[mi][0] = Xs[row    ][col    ];
                a[mi][1] = Xs[row + 8][col    ];
                a[mi][2] = Xs[row    ][col + 4];
                a[mi][3] = Xs[row + 8][col + 4];
            }
            #pragma unroll
            for (int nj = 0; nj < 4; nj++) {
                int kk = ks*8 + qd;
                int nn = wn + nj*8 + g;
                b[nj][0] = Ws[kk    ][nn];
                b[nj][1] = Ws[kk + 4][nn];
            }
            #pragma unroll
            for (int mi = 0; mi < 4; mi++)
                #pragma unroll
                for (int nj = 0; nj < 4; nj++)
                    mma_tf32(acc[mi][nj], a[mi], b[nj]);
        }
        __syncthreads();
    }

    // Epilogue: +bias; q/v -> [b,h,s,d]; k -> transposed [b,h,d,s]
    #pragma unroll
    for (int mi = 0; mi < 4; mi++) {
        #pragma unroll
        for (int half = 0; half < 2; half++) {
            int m = m0 + wm + mi*16 + g + half*8;
            int bb = m >> 11, s = m & 2047;
            #pragma unroll
            for (int nj = 0; nj < 4; nj++) {
                int nn = n0 + wn + nj*8 + 2*qd;
                int h = nn >> 6, d = nn & 63;
                float v0 = acc[mi][nj][half*2 + 0] + bias[h*Dd + d];
                float v1 = acc[mi][nj][half*2 + 1] + bias[h*Dd + d + 1];
                size_t bh = (size_t)bb * Hh + h;
                if (z == 1) {
                    g_kT[(bh*Dd + d    )*Ss + s] = v0;
                    g_kT[(bh*Dd + d + 1)*Ss + s] = v1;
                } else {
                    float* out = (z == 0) ? g_q : g_v;
                    *(float2*)&out[(bh*Ss + s)*Dd + d] = make_float2(v0, v1);
                }
            }
        }
    }
}

// ---------------------------------------------------------------------------
// Kernel 2: g_sk[b,h,s] = 0.5*SCALE*||k[b,h,s,:]||^2  (coalesced over s)
// ---------------------------------------------------------------------------
__global__ __launch_bounds__(256) void knorm_kernel()
{
    int idx = blockIdx.x * 256 + threadIdx.x;   // [bh][s]
    int bh = idx >> 11;
    int s  = idx & 2047;
    const float* kp = g_kT + (size_t)bh * Dd * Ss + s;
    float acc = 0.f;
    #pragma unroll
    for (int d = 0; d < Dd; d++) {
        float v = kp[(size_t)d * Ss];
        acc = fmaf(v, v, acc);
    }
    g_sk[idx] = 0.5f * SCALE * acc;
}

// ---------------------------------------------------------------------------
// Kernel 3: flash attention with tf32 mma.  64 q-rows/block, 4 warps.
// scores = (q.k)*SCALE - 0.5*SCALE*||k||^2  (-0.5||q||^2 cancels in softmax).
// Per warp: m16 rows x 64 cols = 8 m16n8k8 tiles per GEMM.
// Smem (dynamic, 52.5KB): Qs[row][d] p68, KPs[d][key] p68 (reused as P[row][key]),
// Vs[key][dv] p68, sks[64].  All fragment loads bank-conflict-free.
// ---------------------------------------------------------------------------
__global__ __launch_bounds__(128) void flash_kernel()
{
    extern __shared__ unsigned sm[];
    unsigned* Qs  = sm;                 // [64][68]  A: [row][d]
    unsigned* KPs = sm + 64*68;         // [64][68]  B: [d][key] ; later P: [row][key]
    unsigned* Vs  = sm + 2*64*68;       // [64][68]  B: [key][dv]
    float*    sks = (float*)(sm + 3*64*68);  // [64]

    const int bh = blockIdx.y;               // b*16+h
    const int q0 = blockIdx.x * 64;
    const int tid = threadIdx.x;
    const int wid = tid >> 5, lane = tid & 31;
    const int g = lane >> 2, qd = lane & 3;

    const float* Qg  = g_q  + ((size_t)bh * Ss + q0) * Dd;
    const float* KTg = g_kT + (size_t)bh * Dd * Ss;
    const float* Vg  = g_v  + (size_t)bh * Ss * Dd;
    const float* skg = g_sk + (size_t)bh * Ss;

    // Load Q tile [64 rows][64 d] -> Qs[row][d] p68
    #pragma unroll
    for (int u = 0; u < 8; u++) {
        int idx = u * 128 + tid;
        int r = idx >> 4, c4 = (idx & 15) << 2;
        float4 xv = *(const float4*)(Qg + (size_t)r * Dd + c4);
        uint4 t = make_uint4(f2tf(xv.x), f2tf(xv.y), f2tf(xv.z), f2tf(xv.w));
        *(uint4*)&Qs[r*68 + c4] = t;
    }

    float m0r = -3.0e38f, m1r = -3.0e38f, l0 = 0.f, l1 = 0.f;
    float oacc[8][4];
    #pragma unroll
    for (int j = 0; j < 8; j++)
        #pragma unroll
        for (int r = 0; r < 4; r++) oacc[j][r] = 0.f;

    const int arow = wid*16 + g;

    for (int k0 = 0; k0 < Ss; k0 += 64) {
        __syncthreads();   // prev iteration's mma fragment reads done
        // Load K^T [d][key] and V [key][dv]
        #pragma unroll
        for (int u = 0; u < 8; u++) {
            int idx = u * 128 + tid;
            int r = idx >> 4, c4 = (idx & 15) << 2;
            float4 kv = *(const float4*)(KTg + (size_t)r * Ss + k0 + c4);
            *(uint4*)&KPs[r*68 + c4] = make_uint4(f2tf(kv.x), f2tf(kv.y), f2tf(kv.z), f2tf(kv.w));
            float4 vv = *(const float4*)(Vg + (size_t)(k0 + r) * Dd + c4);
            *(uint4*)&Vs[r*68 + c4] = make_uint4(f2tf(vv.x), f2tf(vv.y), f2tf(vv.z), f2tf(vv.w));
        }
        if (tid < 64) sks[tid] = skg[k0 + tid];
        __syncthreads();

        // ---- scores mma: sc[j] covers cols [j*8, j*8+8) ----
        float sc[8][4];
        #pragma unroll
        for (int j = 0; j < 8; j++)
            #pragma unroll
            for (int r = 0; r < 4; r++) sc[j][r] = 0.f;

        #pragma unroll
        for (int d0 = 0; d0 < 64; d0 += 8) {
            unsigned a[4];
            a[0] = Qs[ arow     *68 + d0 + qd    ];
            a[1] = Qs[(arow + 8)*68 + d0 + qd    ];
            a[2] = Qs[ arow     *68 + d0 + qd + 4];
            a[3] = Qs[(arow + 8)*68 + d0 + qd + 4];
            #pragma unroll
            for (int j = 0; j < 8; j++) {
                unsigned b[2];
                b[0] = KPs[(d0 + qd    )*68 + j*8 + g];
                b[1] = KPs[(d0 + qd + 4)*68 + j*8 + g];
                mma_tf32(sc[j], a, b);
            }
        }

        // ---- online softmax (rows arow, arow+8; cols j*8+2qd+{0,1}) ----
        float mx0 = -3.0e38f, mx1 = -3.0e38f;
        #pragma unroll
        for (int j = 0; j < 8; j++) {
            #pragma unroll
            for (int c = 0; c < 2; c++) {
                float skc = sks[j*8 + 2*qd + c];
                sc[j][c]   = fmaf(sc[j][c],   SCALE, -skc);
                sc[j][2+c] = fmaf(sc[j][2+c], SCALE, -skc);
                mx0 = fmaxf(mx0, sc[j][c]);
                mx1 = fmaxf(mx1, sc[j][2+c]);
            }
        }
        mx0 = fmaxf(mx0, __shfl_xor_sync(0xffffffffu, mx0, 1));
        mx0 = fmaxf(mx0, __shfl_xor_sync(0xffffffffu, mx0, 2));
        mx1 = fmaxf(mx1, __shfl_xor_sync(0xffffffffu, mx1, 1));
        mx1 = fmaxf(mx1, __shfl_xor_sync(0xffffffffu, mx1, 2));

        float mn0 = fmaxf(m0r, mx0), mn1 = fmaxf(m1r, mx1);
        float al0 = __expf(m0r - mn0), al1 = __expf(m1r - mn1);
        m0r = mn0; m1r = mn1;

        float ps0 = 0.f, ps1 = 0.f;
        #pragma unroll
        for (int j = 0; j < 8; j++) {
            #pragma unroll
            for (int c = 0; c < 2; c++) {
                sc[j][c]   = __expf(sc[j][c]   - mn0); ps0 += sc[j][c];
                sc[j][2+c] = __expf(sc[j][2+c] - mn1); ps1 += sc[j][2+c];
            }
        }
        ps0 += __shfl_xor_sync(0xffffffffu, ps0, 1);
        ps0 += __shfl_xor_sync(0xffffffffu, ps0, 2);
        ps1 += __shfl_xor_sync(0xffffffffu, ps1, 1);
        ps1 += __shfl_xor_sync(0xffffffffu, ps1, 2);
        l0 = l0 * al0 + ps0;
        l1 = l1 * al1 + ps1;
        #pragma unroll
        for (int j = 0; j < 8; j++) {
            oacc[j][0] *= al0; oacc[j][1] *= al0;
            oacc[j][2] *= al1; oacc[j][3] *= al1;
        }

        __syncthreads();   // all warps done reading KPs (K) before overwrite with P
        // Store P into KPs as [row][key] p68 (uint2: two contiguous cols)
        #pragma unroll
        for (int j = 0; j < 8; j++) {
            int col = j*8 + 2*qd;
            *(uint2*)&KPs[ arow     *68 + col] = make_uint2(f2tf(sc[j][0]), f2tf(sc[j][1]));
            *(uint2*)&KPs[(arow + 8)*68 + col] = make_uint2(f2tf(sc[j][2]), f2tf(sc[j][3]));
        }
        __syncthreads();

        // ---- PV mma: oacc += P[row][key] * V[key][dv] ----
        #pragma unroll
        for (int kk0 = 0; kk0 < 64; kk0 += 8) {
            unsigned a[4];
            a[0] = KPs[ arow     *68 + kk0 + qd    ];
            a[1] = KPs[(arow + 8)*68 + kk0 + qd    ];
            a[2] = KPs[ arow     *68 + kk0 + qd + 4];
            a[3] = KPs[(arow + 8)*68 + kk0 + qd + 4];
            #pragma unroll
            for (int j = 0; j < 8; j++) {
                unsigned b[2];
                b[0] = Vs[(kk0 + qd    )*68 + j*8 + g];
                b[1] = Vs[(kk0 + qd + 4)*68 + j*8 + g];
                mma_tf32(oacc[j], a, b);
            }
        }
    }

    // Epilogue: normalize, write concat layout g_att[b, s, h*64 + dv]
    const int b = bh >> 4, h = bh & 15;
    const int s0 = q0 + arow, s1 = s0 + 8;
    float inv0 = 1.0f / l0, inv1 = 1.0f / l1;
    #pragma unroll
    for (int j = 0; j < 8; j++) {
        int col = h*Dd + j*8 + 2*qd;
        *(float2*)&g_att[((size_t)b*Ss + s0)*Ee + col] =
            make_float2(oacc[j][0]*inv0, oacc[j][1]*inv0);
        *(float2*)&g_att[((size_t)b*Ss + s1)*Ee + col] =
            make_float2(oacc[j][2]*inv1, oacc[j][3]*inv1);
    }
}

// ---------------------------------------------------------------------------
// Kernel 4: residual add + custom LayerNorm (ddof=1, shift in divisor).
// ---------------------------------------------------------------------------
__global__ __launch_bounds__(256) void ln_kernel(
    const float* __restrict__ resid, const float* __restrict__ gamma,
    const float* __restrict__ beta, float* __restrict__ out)
{
    const int row = blockIdx.x;            // 0..4095
    const float* xa = g_att + (size_t)row * Ee;
    const float* xr = resid + (size_t)row * Ee;
    const int tid = threadIdx.x;

    float4 a = *(const float4*)(xa + tid*4);
    float4 r = *(const float4*)(xr + tid*4);
    float x0 = a.x + r.x, x1 = a.y + r.y, x2 = a.z + r.z, x3 = a.w + r.w;

    float sum = x0 + x1 + x2 + x3;
    float sq  = x0*x0 + x1*x1 + x2*x2 + x3*x3;
    #pragma unroll
    for (int o = 16; o >= 1; o >>= 1) {
        sum += __shfl_xor_sync(0xffffffffu, sum, o);
        sq  += __shfl_xor_sync(0xffffffffu, sq,  o);
    }
    __shared__ float rs[8], rq[8];
    int w = tid >> 5, lane = tid & 31;
    if (lane == 0) { rs[w] = sum; rq[w] = sq; }
    __syncthreads();
    float ts = 0.f, tq = 0.f;
    #pragma unroll
    for (int i = 0; i < 8; i++) { ts += rs[i]; tq += rq[i]; }

    float mean = ts * (1.0f/1024.0f);
    float var  = (tq - 1024.0f * mean * mean) * (1.0f/1023.0f);  // ddof=1
    float stdv = sqrtf(var);

    float4 gv = *(const float4*)(gamma + tid*4);
    float4 bv = *(const float4*)(beta  + tid*4);
    float4 o4;
    o4.x = gv.x * (x0 - mean) / (stdv + 1e-6f + bv.x);
    o4.y = gv.y * (x1 - mean) / (stdv + 1e-6f + bv.y);
    o4.z = gv.z * (x2 - mean) / (stdv + 1e-6f + bv.z);
    o4.w = gv.w * (x3 - mean) / (stdv + 1e-6f + bv.w);
    *(float4*)(out + (size_t)row * Ee + tid*4) = o4;
}

// ---------------------------------------------------------------------------
// Launch.  Inputs: query, key, value, residual_x, Wq, bq, Wk, bk, Wv, bv,
// scale, shift.  Output: float32 [2,2048,1024].
// ---------------------------------------------------------------------------
extern "C" void kernel_launch(void* const* d_in, const int* in_sizes, int n_in,
                              void* d_out, int out_size)
{
    (void)in_sizes; (void)n_in; (void)out_size;
    const float* query = (const float*)d_in[0];
    const float* key   = (const float*)d_in[1];
    const float* value = (const float*)d_in[2];
    const float* resid = (const float*)d_in[3];
    const float* Wq = (const float*)d_in[4];
    const float* bq = (const float*)d_in[5];
    const float* Wk = (const float*)d_in[6];
    const float* bk = (const float*)d_in[7];
    const float* Wv = (const float*)d_in[8];
    const float* bv = (const float*)d_in[9];
    const float* gamma = (const float*)d_in[10];
    const float* beta  = (const float*)d_in[11];
    float* out = (float*)d_out;

    const int flash_smem = (3*64*68 + 64) * 4;   // 52480 B
    cudaFuncSetAttribute(flash_kernel,
                         cudaFuncAttributeMaxDynamicSharedMemorySize, flash_smem);

    dim3 gproj(32, 8, 3);                  // 4096/128 m-tiles, 1024/128 n-tiles, {Q,K,V}
    proj_kernel<<<gproj, 256>>>(query, key, value, Wq, Wk, Wv, bq, bk, bv);
    knorm_kernel<<<256, 256>>>();          // 65536 rows
    flash_kernel<<<dim3(32, 32), 128, flash_smem>>>();
    ln_kernel<<<4096, 256>>>(resid, gamma, beta, out);
}

// round 3
// speedup vs baseline: 4.7295x; 1.9969x over previous
#include <cuda_runtime.h>
#include <cuda_bf16.h>

// Problem constants
#define Bb 2
#define Ss 2048
#define Ee 1024
#define Hh 16
#define Dd 64
#define SCALE (1.0f/32.0f)   // 1/sqrt(E)

// ---------------------------------------------------------------------------
// Scratch (device globals; allocation inside kernel_launch is forbidden)
// ---------------------------------------------------------------------------
__device__ __nv_bfloat16 g_q  [(size_t)Bb*Hh*Ss*Dd];   // [b,h,s,d]
__device__ __nv_bfloat16 g_kT [(size_t)Bb*Hh*Dd*Ss];   // [b,h,d,s] (transposed K)
__device__ __nv_bfloat16 g_v  [(size_t)Bb*Hh*Ss*Dd];   // [b,h,s,d]
__device__ float         g_sk [(size_t)Bb*Hh*Ss];      // 0.5*SCALE*||k||^2
__device__ float         g_att[(size_t)Bb*Ss*Ee];      // attention out, [b,s,e]

// ---------------------------------------------------------------------------
// Helpers
// ---------------------------------------------------------------------------
__device__ __forceinline__ unsigned s2u(const void* p) {
    return (unsigned)__cvta_generic_to_shared(p);
}
__device__ __forceinline__ unsigned f22bf(float x, float y) {
    __nv_bfloat162 h = __floats2bfloat162_rn(x, y);
    return *(unsigned*)&h;
}
__device__ __forceinline__ void mma_bf16(float* c, const unsigned* a, const unsigned* b) {
    asm volatile(
        "mma.sync.aligned.m16n8k16.row.col.f32.bf16.bf16.f32 "
        "{%0,%1,%2,%3}, {%4,%5,%6,%7}, {%8,%9}, {%0,%1,%2,%3};"
        : "+f"(c[0]), "+f"(c[1]), "+f"(c[2]), "+f"(c[3])
        : "r"(a[0]), "r"(a[1]), "r"(a[2]), "r"(a[3]), "r"(b[0]), "r"(b[1]));
}
// A fragment (row-major m16k16): 4 regs via ldmatrix.x4
__device__ __forceinline__ void ldmA(unsigned* a, unsigned saddr) {
    asm volatile("ldmatrix.sync.aligned.m8n8.x4.shared.b16 {%0,%1,%2,%3}, [%4];"
        : "=r"(a[0]), "=r"(a[1]), "=r"(a[2]), "=r"(a[3]) : "r"(saddr));
}
// B fragment (col-major k16n8) from [k][n] smem: 2 regs via ldmatrix.x2.trans
__device__ __forceinline__ void ldmB(unsigned* b, unsigned saddr) {
    asm volatile("ldmatrix.sync.aligned.m8n8.x2.trans.shared.b16 {%0,%1}, [%2];"
        : "=r"(b[0]), "=r"(b[1]) : "r"(saddr));
}

// ---------------------------------------------------------------------------
// Kernel 1: fused QKV projection, bf16 m16n8k16 mma, fp32 accum.
// Block tile 128x128, K-chunk 32 (2 k16 steps). 8 warps, warp tile 64x32.
// Xs[m][k] pitch 40 halves; Ws[k][n] pitch 136 halves (ldmatrix.trans for B).
// Outputs bf16: q/v -> [b,h,s,d]; k -> transposed [b,h,d,s].
// ---------------------------------------------------------------------------
__global__ __launch_bounds__(256) void proj_kernel(
    const float* __restrict__ Xq, const float* __restrict__ Xk, const float* __restrict__ Xv,
    const float* __restrict__ Wq, const float* __restrict__ Wk, const float* __restrict__ Wv,
    const float* __restrict__ Bq, const float* __restrict__ Bk, const float* __restrict__ Bv)
{
    const int z = blockIdx.z;
    const float* X    = (z==0) ? Xq : ((z==1) ? Xk : Xv);
    const float* W    = (z==0) ? Wq : ((z==1) ? Wk : Wv);
    const float* bias = (z==0) ? Bq : ((z==1) ? Bk : Bv);

    __shared__ __nv_bfloat16 Xs[128][40];   // [m][k0..31], pad 8
    __shared__ __nv_bfloat16 Ws[32][136];   // [k][n0..127], pad 8

    const int tid  = threadIdx.x;
    const int wid  = tid >> 5, lane = tid & 31;
    const int g    = lane >> 2, qd = lane & 3;
    const int wm   = (wid & 1) * 64;
    const int wn   = (wid >> 1) * 32;
    const int m0   = blockIdx.x * 128;
    const int n0   = blockIdx.y * 128;

    // ldmatrix lane addressing components
    const int arow_l = (lane & 7) + ((lane >> 3) & 1) * 8;   // row within m16 tile
    const int acol_l = (lane >> 4) * 8;                       // k offset within k16
    const int brow_l = (lane & 7) + ((lane >> 3) & 1) * 8;   // k row within k16 (lanes 16-31 dup)

    float acc[4][4][4];
    #pragma unroll
    for (int mi = 0; mi < 4; mi++)
        #pragma unroll
        for (int nj = 0; nj < 4; nj++)
            #pragma unroll
            for (int r = 0; r < 4; r++) acc[mi][nj][r] = 0.f;

    for (int k0 = 0; k0 < Ee; k0 += 32) {
        // X tile [128][32] -> bf16
        #pragma unroll
        for (int u = 0; u < 4; u++) {
            int idx = u * 256 + tid;
            int r = idx >> 3, c4 = (idx & 7) << 2;
            float4 xv = *(const float4*)(X + (size_t)(m0 + r) * Ee + k0 + c4);
            uint2 t = make_uint2(f22bf(xv.x, xv.y), f22bf(xv.z, xv.w));
            *(uint2*)&Xs[r][c4] = t;
        }
        // W tile [32][128]; n -> (h=n>>6, d=n&63)
        #pragma unroll
        for (int u = 0; u < 4; u++) {
            int idx = u * 256 + tid;
            int kk = idx >> 5, c4 = (idx & 31) << 2;
            int n = n0 + c4;
            int h = n >> 6, d = n & 63;
            float4 wv = *(const float4*)(W + (size_t)h * (Ee*Dd) + (size_t)(k0 + kk) * Dd + d);
            uint2 t = make_uint2(f22bf(wv.x, wv.y), f22bf(wv.z, wv.w));
            *(uint2*)&Ws[kk][c4] = t;
        }
        __syncthreads();

        #pragma unroll
        for (int ks = 0; ks < 2; ks++) {
            unsigned a[4][4], b[4][2];
            #pragma unroll
            for (int mi = 0; mi < 4; mi++)
                ldmA(a[mi], s2u(&Xs[wm + mi*16 + arow_l][ks*16 + acol_l]));
            #pragma unroll
            for (int nj = 0; nj < 4; nj++)
                ldmB(b[nj], s2u(&Ws[ks*16 + brow_l][wn + nj*8]));
            #pragma unroll
            for (int mi = 0; mi < 4; mi++)
                #pragma unroll
                for (int nj = 0; nj < 4; nj++)
                    mma_bf16(acc[mi][nj], a[mi], b[nj]);
        }
        __syncthreads();
    }

    // Epilogue: +bias, convert to bf16
    #pragma unroll
    for (int mi = 0; mi < 4; mi++) {
        #pragma unroll
        for (int half = 0; half < 2; half++) {
            int m = m0 + wm + mi*16 + g + half*8;
            int bb = m >> 11, s = m & 2047;
            #pragma unroll
            for (int nj = 0; nj < 4; nj++) {
                int nn = wn + nj*8 + 2*qd;            // within block tile
                int n = n0 + nn;
                int h = n >> 6, d = n & 63;
                float v0 = acc[mi][nj][half*2 + 0] + bias[h*Dd + d];
                float v1 = acc[mi][nj][half*2 + 1] + bias[h*Dd + d + 1];
                size_t bh = (size_t)bb * Hh + h;
                if (z == 1) {
                    g_kT[(bh*Dd + d    )*Ss + s] = __float2bfloat16_rn(v0);
                    g_kT[(bh*Dd + d + 1)*Ss + s] = __float2bfloat16_rn(v1);
                } else {
                    __nv_bfloat16* out = (z == 0) ? g_q : g_v;
                    *(unsigned*)&out[(bh*Ss + s)*Dd + d] = f22bf(v0, v1);
                }
            }
        }
    }
}

// ---------------------------------------------------------------------------
// Kernel 2: g_sk[b,h,s] = 0.5*SCALE*||k||^2 from the SAME bf16 k the mma sees.
// ---------------------------------------------------------------------------
__global__ __launch_bounds__(256) void knorm_kernel()
{
    int idx = blockIdx.x * 256 + threadIdx.x;
    int bh = idx >> 11;
    int s  = idx & 2047;
    const __nv_bfloat16* kp = g_kT + (size_t)bh * Dd * Ss + s;
    float acc = 0.f;
    #pragma unroll
    for (int d = 0; d < Dd; d++) {
        float v = __bfloat162float(kp[(size_t)d * Ss]);
        acc = fmaf(v, v, acc);
    }
    g_sk[idx] = 0.5f * SCALE * acc;
}

// ---------------------------------------------------------------------------
// Kernel 3: flash attention, bf16 m16n8k16. 64 q-rows/block, 4 warps.
// scores = (q.k)*SCALE - 0.5*SCALE*||k||^2 (||q||^2 cancels in softmax).
// Smem (static ~28KB): Qs[row][d] p72, KPs = K [d][key] p72 then P [row][key] p72,
// Vs[key][dv] p72, sks[64]. All fragment paths conflict-free.
// ---------------------------------------------------------------------------
__global__ __launch_bounds__(128) void flash_kernel()
{
    __shared__ __nv_bfloat16 Qs [64][72];
    __shared__ __nv_bfloat16 KPs[64][72];
    __shared__ __nv_bfloat16 Vs [64][72];
    __shared__ float sks[64];

    const int bh = blockIdx.y;
    const int q0 = blockIdx.x * 64;
    const int tid = threadIdx.x;
    const int wid = tid >> 5, lane = tid & 31;
    const int g = lane >> 2, qd = lane & 3;

    const __nv_bfloat16* Qg  = g_q  + ((size_t)bh * Ss + q0) * Dd;
    const __nv_bfloat16* KTg = g_kT + (size_t)bh * Dd * Ss;
    const __nv_bfloat16* Vg  = g_v  + (size_t)bh * Ss * Dd;
    const float*         skg = g_sk + (size_t)bh * Ss;

    const int arow_l = (lane & 7) + ((lane >> 3) & 1) * 8;
    const int acol_l = (lane >> 4) * 8;
    const int brow_l = (lane & 7) + ((lane >> 3) & 1) * 8;

    // Load Q tile [64][64] bf16 (raw copy, no conversion)
    #pragma unroll
    for (int u = 0; u < 4; u++) {
        int idx = u * 128 + tid;
        int r = idx >> 3, c8 = (idx & 7) << 3;
        *(uint4*)&Qs[r][c8] = *(const uint4*)(Qg + (size_t)r * Dd + c8);
    }

    float m0r = -3.0e38f, m1r = -3.0e38f, l0 = 0.f, l1 = 0.f;
    float oacc[8][4];
    #pragma unroll
    for (int j = 0; j < 8; j++)
        #pragma unroll
        for (int r = 0; r < 4; r++) oacc[j][r] = 0.f;

    const int wrow = wid * 16;          // warp's 16-row base
    const int crow = wrow + g;          // this thread's C row (and +8)

    for (int k0 = 0; k0 < Ss; k0 += 64) {
        __syncthreads();
        // K^T [d][key] and V [key][dv], raw bf16 copies
        #pragma unroll
        for (int u = 0; u < 4; u++) {
            int idx = u * 128 + tid;
            int r = idx >> 3, c8 = (idx & 7) << 3;
            *(uint4*)&KPs[r][c8] = *(const uint4*)(KTg + (size_t)r * Ss + k0 + c8);
            *(uint4*)&Vs [r][c8] = *(const uint4*)(Vg  + (size_t)(k0 + r) * Dd + c8);
        }
        if (tid < 64) sks[tid] = skg[k0 + tid];
        __syncthreads();

        // ---- scores: Q[row][d] x K^T[d][key] ----
        float sc[8][4];
        #pragma unroll
        for (int j = 0; j < 8; j++)
            #pragma unroll
            for (int r = 0; r < 4; r++) sc[j][r] = 0.f;

        #pragma unroll
        for (int d0 = 0; d0 < 64; d0 += 16) {
            unsigned a[4];
            ldmA(a, s2u(&Qs[wrow + arow_l][d0 + acol_l]));
            #pragma unroll
            for (int j = 0; j < 8; j++) {
                unsigned b[2];
                ldmB(b, s2u(&KPs[d0 + brow_l][j*8]));
                mma_bf16(sc[j], a, b);
            }
        }

        // ---- online softmax (rows crow, crow+8; cols j*8+2qd+{0,1}) ----
        float mx0 = -3.0e38f, mx1 = -3.0e38f;
        #pragma unroll
        for (int j = 0; j < 8; j++) {
            #pragma unroll
            for (int c = 0; c < 2; c++) {
                float skc = sks[j*8 + 2*qd + c];
                sc[j][c]   = fmaf(sc[j][c],   SCALE, -skc);
                sc[j][2+c] = fmaf(sc[j][2+c], SCALE, -skc);
                mx0 = fmaxf(mx0, sc[j][c]);
                mx1 = fmaxf(mx1, sc[j][2+c]);
            }
        }
        mx0 = fmaxf(mx0, __shfl_xor_sync(0xffffffffu, mx0, 1));
        mx0 = fmaxf(mx0, __shfl_xor_sync(0xffffffffu, mx0, 2));
        mx1 = fmaxf(mx1, __shfl_xor_sync(0xffffffffu, mx1, 1));
        mx1 = fmaxf(mx1, __shfl_xor_sync(0xffffffffu, mx1, 2));

        float mn0 = fmaxf(m0r, mx0), mn1 = fmaxf(m1r, mx1);
        float al0 = __expf(m0r - mn0), al1 = __expf(m1r - mn1);
        m0r = mn0; m1r = mn1;

        float ps0 = 0.f, ps1 = 0.f;
        #pragma unroll
        for (int j = 0; j < 8; j++) {
            #pragma unroll
            for (int c = 0; c < 2; c++) {
                sc[j][c]   = __expf(sc[j][c]   - mn0); ps0 += sc[j][c];
                sc[j][2+c] = __expf(sc[j][2+c] - mn1); ps1 += sc[j][2+c];
            }
        }
        ps0 += __shfl_xor_sync(0xffffffffu, ps0, 1);
        ps0 += __shfl_xor_sync(0xffffffffu, ps0, 2);
        ps1 += __shfl_xor_sync(0xffffffffu, ps1, 1);
        ps1 += __shfl_xor_sync(0xffffffffu, ps1, 2);
        l0 = l0 * al0 + ps0;
        l1 = l1 * al1 + ps1;
        #pragma unroll
        for (int j = 0; j < 8; j++) {
            oacc[j][0] *= al0; oacc[j][1] *= al0;
            oacc[j][2] *= al1; oacc[j][3] *= al1;
        }

        __syncthreads();   // all warps done reading K before P overwrite
        // Store P as [row][key] bf16 pairs (banks 4g+4j+qd: conflict-free)
        #pragma unroll
        for (int j = 0; j < 8; j++) {
            int col = j*8 + 2*qd;
            *(unsigned*)&KPs[crow    ][col] = f22bf(sc[j][0], sc[j][1]);
            *(unsigned*)&KPs[crow + 8][col] = f22bf(sc[j][2], sc[j][3]);
        }
        __syncthreads();

        // ---- PV: P[row][key] x V[key][dv] ----
        #pragma unroll
        for (int kk0 = 0; kk0 < 64; kk0 += 16) {
            unsigned a[4];
            ldmA(a, s2u(&KPs[wrow + arow_l][kk0 + acol_l]));
            #pragma unroll
            for (int j = 0; j < 8; j++) {
                unsigned b[2];
                ldmB(b, s2u(&Vs[kk0 + brow_l][j*8]));
                mma_bf16(oacc[j], a, b);
            }
        }
    }

    // Epilogue: normalize, write fp32 concat layout g_att[b, s, h*64 + dv]
    const int b = bh >> 4, h = bh & 15;
    const int s0 = q0 + crow, s1 = s0 + 8;
    float inv0 = 1.0f / l0, inv1 = 1.0f / l1;
    #pragma unroll
    for (int j = 0; j < 8; j++) {
        int col = h*Dd + j*8 + 2*qd;
        *(float2*)&g_att[((size_t)b*Ss + s0)*Ee + col] =
            make_float2(oacc[j][0]*inv0, oacc[j][1]*inv0);
        *(float2*)&g_att[((size_t)b*Ss + s1)*Ee + col] =
            make_float2(oacc[j][2]*inv1, oacc[j][3]*inv1);
    }
}

// ---------------------------------------------------------------------------
// Kernel 4: residual add + custom LayerNorm (ddof=1, shift in divisor).
// ---------------------------------------------------------------------------
__global__ __launch_bounds__(256) void ln_kernel(
    const float* __restrict__ resid, const float* __restrict__ gamma,
    const float* __restrict__ beta, float* __restrict__ out)
{
    const int row = blockIdx.x;            // 0..4095
    const float* xa = g_att + (size_t)row * Ee;
    const float* xr = resid + (size_t)row * Ee;
    const int tid = threadIdx.x;

    float4 a = *(const float4*)(xa + tid*4);
    float4 r = *(const float4*)(xr + tid*4);
    float x0 = a.x + r.x, x1 = a.y + r.y, x2 = a.z + r.z, x3 = a.w + r.w;

    float sum = x0 + x1 + x2 + x3;
    float sq  = x0*x0 + x1*x1 + x2*x2 + x3*x3;
    #pragma unroll
    for (int o = 16; o >= 1; o >>= 1) {
        sum += __shfl_xor_sync(0xffffffffu, sum, o);
        sq  += __shfl_xor_sync(0xffffffffu, sq,  o);
    }
    __shared__ float rs[8], rq[8];
    int w = tid >> 5, lane = tid & 31;
    if (lane == 0) { rs[w] = sum; rq[w] = sq; }
    __syncthreads();
    float ts = 0.f, tq = 0.f;
    #pragma unroll
    for (int i = 0; i < 8; i++) { ts += rs[i]; tq += rq[i]; }

    float mean = ts * (1.0f/1024.0f);
    float var  = (tq - 1024.0f * mean * mean) * (1.0f/1023.0f);  // ddof=1
    float stdv = sqrtf(var);

    float4 gv = *(const float4*)(gamma + tid*4);
    float4 bv = *(const float4*)(beta  + tid*4);
    float4 o4;
    o4.x = gv.x * (x0 - mean) / (stdv + 1e-6f + bv.x);
    o4.y = gv.y * (x1 - mean) / (stdv + 1e-6f + bv.y);
    o4.z = gv.z * (x2 - mean) / (stdv + 1e-6f + bv.z);
    o4.w = gv.w * (x3 - mean) / (stdv + 1e-6f + bv.w);
    *(float4*)(out + (size_t)row * Ee + tid*4) = o4;
}

// ---------------------------------------------------------------------------
// Launch.  Inputs: query, key, value, residual_x, Wq, bq, Wk, bk, Wv, bv,
// scale, shift.  Output: float32 [2,2048,1024].
// ---------------------------------------------------------------------------
extern "C" void kernel_launch(void* const* d_in, const int* in_sizes, int n_in,
                              void* d_out, int out_size)
{
    (void)in_sizes; (void)n_in; (void)out_size;
    const float* query = (const float*)d_in[0];
    const float* key   = (const float*)d_in[1];
    const float* value = (const float*)d_in[2];
    const float* resid = (const float*)d_in[3];
    const float* Wq = (const float*)d_in[4];
    const float* bq = (const float*)d_in[5];
    const float* Wk = (const float*)d_in[6];
    const float* bk = (const float*)d_in[7];
    const float* Wv = (const float*)d_in[8];
    const float* bv = (const float*)d_in[9];
    const float* gamma = (const float*)d_in[10];
    const float* beta  = (const float*)d_in[11];
    float* out = (float*)d_out;

    dim3 gproj(32, 8, 3);
    proj_kernel<<<gproj, 256>>>(query, key, value, Wq, Wk, Wv, bq, bk, bv);
    knorm_kernel<<<256, 256>>>();
    flash_kernel<<<dim3(32, 32), 128>>>();
    ln_kernel<<<4096, 256>>>(resid, gamma, beta, out);
}

// round 4
// speedup vs baseline: 5.5433x; 1.1721x over previous
#include <cuda_runtime.h>
#include <cuda_bf16.h>

// Problem constants
#define Bb 2
#define Ss 2048
#define Ee 1024
#define Hh 16
#define Dd 64
#define SCALE (1.0f/32.0f)   // 1/sqrt(E)

typedef __nv_bfloat16 bf;

// ---------------------------------------------------------------------------
// Scratch (device globals; allocation inside kernel_launch is forbidden)
// ---------------------------------------------------------------------------
__device__ bf    g_q  [(size_t)Bb*Hh*Ss*Dd];   // [b,h,s,d]
__device__ bf    g_kT [(size_t)Bb*Hh*Dd*Ss];   // [b,h,d,s] (transposed K)
__device__ bf    g_v  [(size_t)Bb*Hh*Ss*Dd];   // [b,h,s,d]
__device__ float g_sk [(size_t)Bb*Hh*Ss];      // 0.5*SCALE*||k||^2
__device__ float g_att[(size_t)Bb*Ss*Ee];      // attention out, [b,s,e]

// ---------------------------------------------------------------------------
// Helpers
// ---------------------------------------------------------------------------
__device__ __forceinline__ unsigned s2u(const void* p) {
    return (unsigned)__cvta_generic_to_shared(p);
}
__device__ __forceinline__ unsigned f22bf(float x, float y) {
    __nv_bfloat162 h = __floats2bfloat162_rn(x, y);
    return *(unsigned*)&h;
}
__device__ __forceinline__ void mma_bf16(float* c, const unsigned* a, const unsigned* b) {
    asm volatile(
        "mma.sync.aligned.m16n8k16.row.col.f32.bf16.bf16.f32 "
        "{%0,%1,%2,%3}, {%4,%5,%6,%7}, {%8,%9}, {%0,%1,%2,%3};"
        : "+f"(c[0]), "+f"(c[1]), "+f"(c[2]), "+f"(c[3])
        : "r"(a[0]), "r"(a[1]), "r"(a[2]), "r"(a[3]), "r"(b[0]), "r"(b[1]));
}
__device__ __forceinline__ void ldmA(unsigned* a, unsigned saddr) {
    asm volatile("ldmatrix.sync.aligned.m8n8.x4.shared.b16 {%0,%1,%2,%3}, [%4];"
        : "=r"(a[0]), "=r"(a[1]), "=r"(a[2]), "=r"(a[3]) : "r"(saddr));
}
__device__ __forceinline__ void ldmB(unsigned* b, unsigned saddr) {
    asm volatile("ldmatrix.sync.aligned.m8n8.x2.trans.shared.b16 {%0,%1}, [%2];"
        : "=r"(b[0]), "=r"(b[1]) : "r"(saddr));
}
__device__ __forceinline__ void cp16(unsigned dst, const void* src) {
    asm volatile("cp.async.cg.shared.global [%0], [%1], 16;" :: "r"(dst), "l"(src));
}
#define CP_COMMIT() asm volatile("cp.async.commit_group;")
#define CP_WAIT0()  asm volatile("cp.async.wait_group 0;")

// ---------------------------------------------------------------------------
// Kernel 1: fused QKV projection, bf16 m16n8k16, fp32 accum.
// Block tile 128x128, K-chunk 32.  Double-buffered smem + register prefetch:
// one __syncthreads per chunk, gmem latency hidden behind mma.
// ---------------------------------------------------------------------------
__global__ __launch_bounds__(256, 2) void proj_kernel(
    const float* __restrict__ Xq, const float* __restrict__ Xk, const float* __restrict__ Xv,
    const float* __restrict__ Wq, const float* __restrict__ Wk, const float* __restrict__ Wv,
    const float* __restrict__ Bq, const float* __restrict__ Bk, const float* __restrict__ Bv)
{
    const int z = blockIdx.z;
    const float* X    = (z==0) ? Xq : ((z==1) ? Xk : Xv);
    const float* W    = (z==0) ? Wq : ((z==1) ? Wk : Wv);
    const float* bias = (z==0) ? Bq : ((z==1) ? Bk : Bv);

    __shared__ bf Xs[2][128][40];   // [buf][m][k], pad 8
    __shared__ bf Ws[2][32][136];   // [buf][k][n], pad 8

    const int tid  = threadIdx.x;
    const int wid  = tid >> 5, lane = tid & 31;
    const int g    = lane >> 2, qd = lane & 3;
    const int wm   = (wid & 1) * 64;
    const int wn   = (wid >> 1) * 32;
    const int m0   = blockIdx.x * 128;
    const int n0   = blockIdx.y * 128;

    const int arow_l = (lane & 7) + ((lane >> 3) & 1) * 8;
    const int acol_l = (lane >> 4) * 8;
    const int brow_l = (lane & 7) + ((lane >> 3) & 1) * 8;

    // prefetch-register addressing (fixed per thread)
    const int xr_r  = tid >> 3,  xr_c = (tid & 7) << 2;     // +u*32 rows
    const int wr_k  = tid >> 5,  wr_c = (tid & 31) << 2;    // +u*8 k-rows
    const int wn_h  = (n0 + wr_c) >> 6, wn_d = (n0 + wr_c) & 63;

    uint2 xr[4], wr[4];
    auto prefetch = [&](int k0) {
        #pragma unroll
        for (int u = 0; u < 4; u++) {
            float4 xv = *(const float4*)(X + (size_t)(m0 + xr_r + u*32) * Ee + k0 + xr_c);
            xr[u] = make_uint2(f22bf(xv.x, xv.y), f22bf(xv.z, xv.w));
            float4 wv = *(const float4*)(W + (size_t)wn_h * (Ee*Dd)
                                           + (size_t)(k0 + wr_k + u*8) * Dd + wn_d);
            wr[u] = make_uint2(f22bf(wv.x, wv.y), f22bf(wv.z, wv.w));
        }
    };

    float acc[4][4][4];
    #pragma unroll
    for (int mi = 0; mi < 4; mi++)
        #pragma unroll
        for (int nj = 0; nj < 4; nj++)
            #pragma unroll
            for (int r = 0; r < 4; r++) acc[mi][nj][r] = 0.f;

    prefetch(0);

    for (int k0 = 0; k0 < Ee; k0 += 32) {
        const int buf = (k0 >> 5) & 1;
        #pragma unroll
        for (int u = 0; u < 4; u++) {
            *(uint2*)&Xs[buf][xr_r + u*32][xr_c] = xr[u];
            *(uint2*)&Ws[buf][wr_k + u*8][wr_c] = wr[u];
        }
        __syncthreads();
        if (k0 + 32 < Ee) prefetch(k0 + 32);   // overlapped with mma below

        #pragma unroll
        for (int ks = 0; ks < 2; ks++) {
            unsigned a[4][4], b[4][2];
            #pragma unroll
            for (int mi = 0; mi < 4; mi++)
                ldmA(a[mi], s2u(&Xs[buf][wm + mi*16 + arow_l][ks*16 + acol_l]));
            #pragma unroll
            for (int nj = 0; nj < 4; nj++)
                ldmB(b[nj], s2u(&Ws[buf][ks*16 + brow_l][wn + nj*8]));
            #pragma unroll
            for (int mi = 0; mi < 4; mi++)
                #pragma unroll
                for (int nj = 0; nj < 4; nj++)
                    mma_bf16(acc[mi][nj], a[mi], b[nj]);
        }
        // no trailing sync: next iter writes the other buffer, whose readers
        // finished before this iteration's __syncthreads
    }

    // Epilogue: +bias, convert to bf16
    #pragma unroll
    for (int mi = 0; mi < 4; mi++) {
        #pragma unroll
        for (int half = 0; half < 2; half++) {
            int m = m0 + wm + mi*16 + g + half*8;
            int bb = m >> 11, s = m & 2047;
            #pragma unroll
            for (int nj = 0; nj < 4; nj++) {
                int n = n0 + wn + nj*8 + 2*qd;
                int h = n >> 6, d = n & 63;
                float v0 = acc[mi][nj][half*2 + 0] + bias[h*Dd + d];
                float v1 = acc[mi][nj][half*2 + 1] + bias[h*Dd + d + 1];
                size_t bh = (size_t)bb * Hh + h;
                if (z == 1) {
                    g_kT[(bh*Dd + d    )*Ss + s] = __float2bfloat16_rn(v0);
                    g_kT[(bh*Dd + d + 1)*Ss + s] = __float2bfloat16_rn(v1);
                } else {
                    bf* out = (z == 0) ? g_q : g_v;
                    *(unsigned*)&out[(bh*Ss + s)*Dd + d] = f22bf(v0, v1);
                }
            }
        }
    }
}

// ---------------------------------------------------------------------------
// Kernel 2: g_sk = 0.5*SCALE*||k||^2 from the SAME bf16 k the mma consumes.
// ---------------------------------------------------------------------------
__global__ __launch_bounds__(256) void knorm_kernel()
{
    int idx = blockIdx.x * 256 + threadIdx.x;
    int bh = idx >> 11;
    int s  = idx & 2047;
    const bf* kp = g_kT + (size_t)bh * Dd * Ss + s;
    float acc = 0.f;
    #pragma unroll
    for (int d = 0; d < Dd; d++) {
        float v = __bfloat162float(kp[(size_t)d * Ss]);
        acc = fmaf(v, v, acc);
    }
    g_sk[idx] = 0.5f * SCALE * acc;
}

// ---------------------------------------------------------------------------
// Kernel 3: flash attention, bf16 m16n8k16.  64 q-rows/block, 4 warps.
//  - Q A-fragments hoisted to registers (loop-invariant).
//  - P never touches smem: score C-fragment layout == PV A-fragment layout.
//  - K/V double-buffered via cp.async; ONE __syncthreads per k-tile.
//  - ||k||^2 row (8KB) loaded once per block.
// Static smem 45KB: Ks[2] (Q staging aliases Ks), Vs[2], sks[2048].
// ---------------------------------------------------------------------------
__global__ __launch_bounds__(128) void flash_kernel()
{
    __shared__ __align__(16) unsigned char smbuf[45056];
    bf* Ks[2] = { (bf*)smbuf,            (bf*)(smbuf +  9216) };   // [64][72]
    bf* Vs[2] = { (bf*)(smbuf + 18432),  (bf*)(smbuf + 27648) };   // [64][72]
    float* sks = (float*)(smbuf + 36864);                          // [2048]

    const int bh = blockIdx.y;
    const int q0 = blockIdx.x * 64;
    const int tid = threadIdx.x;
    const int wid = tid >> 5, lane = tid & 31;
    const int g = lane >> 2, qd = lane & 3;

    const bf* Qg   = g_q  + ((size_t)bh * Ss + q0) * Dd;
    const bf* KTg  = g_kT + (size_t)bh * Dd * Ss;
    const bf* Vg   = g_v  + (size_t)bh * Ss * Dd;
    const float* skg = g_sk + (size_t)bh * Ss;

    const int arow_l = (lane & 7) + ((lane >> 3) & 1) * 8;
    const int acol_l = (lane >> 4) * 8;
    const int brow_l = (lane & 7) + ((lane >> 3) & 1) * 8;
    const int wrow = wid * 16;
    const int crow = wrow + g;

    const int ld_r  = tid >> 3;            // 0..15, +u*16 rows
    const int ld_c8 = (tid & 7) << 3;      // 0,8,..,56

    // ---- Prologue: Q -> smem (staged in Ks[0]) -> A registers; sks row ----
    {
        bf* Qst = Ks[0];
        #pragma unroll
        for (int u = 0; u < 4; u++)
            *(uint4*)&Qst[(ld_r + u*16)*72 + ld_c8] =
                *(const uint4*)(Qg + (size_t)(ld_r + u*16) * Dd + ld_c8);
        #pragma unroll
        for (int u = 0; u < 4; u++) {
            int idx = u * 128 + tid;
            *(float4*)&sks[idx*4] = *(const float4*)(skg + idx*4);
        }
        __syncthreads();
    }
    unsigned qa[4][4];
    #pragma unroll
    for (int t = 0; t < 4; t++)
        ldmA(qa[t], s2u(&Ks[0][(wrow + arow_l)*72 + t*16 + acol_l]));
    __syncthreads();   // everyone done reading Q staging before cp.async overwrites

    auto issue_loads = [&](int buf, int k0) {
        #pragma unroll
        for (int u = 0; u < 4; u++) {
            int r = ld_r + u*16;
            cp16(s2u(&Ks[buf][r*72 + ld_c8]), KTg + (size_t)r * Ss + k0 + ld_c8);
            cp16(s2u(&Vs[buf][r*72 + ld_c8]), Vg  + (size_t)(k0 + r) * Dd + ld_c8);
        }
        CP_COMMIT();
    };
    issue_loads(0, 0);

    float m0r = -3.0e38f, m1r = -3.0e38f, l0 = 0.f, l1 = 0.f;
    float oacc[8][4];
    #pragma unroll
    for (int j = 0; j < 8; j++)
        #pragma unroll
        for (int r = 0; r < 4; r++) oacc[j][r] = 0.f;

    for (int it = 0; it < Ss/64; it++) {
        const int k0 = it * 64;
        const int buf = it & 1;
        CP_WAIT0();
        __syncthreads();
        if (it + 1 < Ss/64) issue_loads(buf ^ 1, k0 + 64);

        // ---- scores: Q(reg) x K^T[d][key] ----
        float sc[8][4];
        #pragma unroll
        for (int j = 0; j < 8; j++)
            #pragma unroll
            for (int r = 0; r < 4; r++) sc[j][r] = 0.f;

        #pragma unroll
        for (int t = 0; t < 4; t++) {
            #pragma unroll
            for (int j = 0; j < 8; j++) {
                unsigned b[2];
                ldmB(b, s2u(&Ks[buf][(t*16 + brow_l)*72 + j*8]));
                mma_bf16(sc[j], qa[t], b);
            }
        }

        // ---- online softmax (rows crow/crow+8; cols j*8+2qd+{0,1}) ----
        float mx0 = -3.0e38f, mx1 = -3.0e38f;
        #pragma unroll
        for (int j = 0; j < 8; j++) {
            #pragma unroll
            for (int c = 0; c < 2; c++) {
                float skc = sks[k0 + j*8 + 2*qd + c];
                sc[j][c]   = fmaf(sc[j][c],   SCALE, -skc);
                sc[j][2+c] = fmaf(sc[j][2+c], SCALE, -skc);
                mx0 = fmaxf(mx0, sc[j][c]);
                mx1 = fmaxf(mx1, sc[j][2+c]);
            }
        }
        mx0 = fmaxf(mx0, __shfl_xor_sync(0xffffffffu, mx0, 1));
        mx0 = fmaxf(mx0, __shfl_xor_sync(0xffffffffu, mx0, 2));
        mx1 = fmaxf(mx1, __shfl_xor_sync(0xffffffffu, mx1, 1));
        mx1 = fmaxf(mx1, __shfl_xor_sync(0xffffffffu, mx1, 2));

        float mn0 = fmaxf(m0r, mx0), mn1 = fmaxf(m1r, mx1);
        float al0 = __expf(m0r - mn0), al1 = __expf(m1r - mn1);
        m0r = mn0; m1r = mn1;

        float ps0 = 0.f, ps1 = 0.f;
        #pragma unroll
        for (int j = 0; j < 8; j++) {
            #pragma unroll
            for (int c = 0; c < 2; c++) {
                sc[j][c]   = __expf(sc[j][c]   - mn0); ps0 += sc[j][c];
                sc[j][2+c] = __expf(sc[j][2+c] - mn1); ps1 += sc[j][2+c];
            }
        }
        ps0 += __shfl_xor_sync(0xffffffffu, ps0, 1);
        ps0 += __shfl_xor_sync(0xffffffffu, ps0, 2);
        ps1 += __shfl_xor_sync(0xffffffffu, ps1, 1);
        ps1 += __shfl_xor_sync(0xffffffffu, ps1, 2);
        l0 = l0 * al0 + ps0;
        l1 = l1 * al1 + ps1;
        #pragma unroll
        for (int j = 0; j < 8; j++) {
            oacc[j][0] *= al0; oacc[j][1] *= al0;
            oacc[j][2] *= al1; oacc[j][3] *= al1;
        }

        // ---- PV: P straight from registers (C-frag == A-frag layout) ----
        #pragma unroll
        for (int t = 0; t < 4; t++) {
            unsigned a[4];
            a[0] = f22bf(sc[2*t  ][0], sc[2*t  ][1]);
            a[1] = f22bf(sc[2*t  ][2], sc[2*t  ][3]);
            a[2] = f22bf(sc[2*t+1][0], sc[2*t+1][1]);
            a[3] = f22bf(sc[2*t+1][2], sc[2*t+1][3]);
            #pragma unroll
            for (int j = 0; j < 8; j++) {
                unsigned b[2];
                ldmB(b, s2u(&Vs[buf][(t*16 + brow_l)*72 + j*8]));
                mma_bf16(oacc[j], a, b);
            }
        }
    }

    // Epilogue: normalize, write fp32 concat layout g_att[b, s, h*64 + dv]
    const int b = bh >> 4, h = bh & 15;
    const int s0 = q0 + crow, s1 = s0 + 8;
    float inv0 = 1.0f / l0, inv1 = 1.0f / l1;
    #pragma unroll
    for (int j = 0; j < 8; j++) {
        int col = h*Dd + j*8 + 2*qd;
        *(float2*)&g_att[((size_t)b*Ss + s0)*Ee + col] =
            make_float2(oacc[j][0]*inv0, oacc[j][1]*inv0);
        *(float2*)&g_att[((size_t)b*Ss + s1)*Ee + col] =
            make_float2(oacc[j][2]*inv1, oacc[j][3]*inv1);
    }
}

// ---------------------------------------------------------------------------
// Kernel 4: residual add + custom LayerNorm (ddof=1, shift in divisor).
// ---------------------------------------------------------------------------
__global__ __launch_bounds__(256) void ln_kernel(
    const float* __restrict__ resid, const float* __restrict__ gamma,
    const float* __restrict__ beta, float* __restrict__ out)
{
    const int row = blockIdx.x;            // 0..4095
    const float* xa = g_att + (size_t)row * Ee;
    const float* xr = resid + (size_t)row * Ee;
    const int tid = threadIdx.x;

    float4 a = *(const float4*)(xa + tid*4);
    float4 r = *(const float4*)(xr + tid*4);
    float x0 = a.x + r.x, x1 = a.y + r.y, x2 = a.z + r.z, x3 = a.w + r.w;

    float sum = x0 + x1 + x2 + x3;
    float sq  = x0*x0 + x1*x1 + x2*x2 + x3*x3;
    #pragma unroll
    for (int o = 16; o >= 1; o >>= 1) {
        sum += __shfl_xor_sync(0xffffffffu, sum, o);
        sq  += __shfl_xor_sync(0xffffffffu, sq,  o);
    }
    __shared__ float rs[8], rq[8];
    int w = tid >> 5, lane = tid & 31;
    if (lane == 0) { rs[w] = sum; rq[w] = sq; }
    __syncthreads();
    float ts = 0.f, tq = 0.f;
    #pragma unroll
    for (int i = 0; i < 8; i++) { ts += rs[i]; tq += rq[i]; }

    float mean = ts * (1.0f/1024.0f);
    float var  = (tq - 1024.0f * mean * mean) * (1.0f/1023.0f);  // ddof=1
    float stdv = sqrtf(var);

    float4 gv = *(const float4*)(gamma + tid*4);
    float4 bv = *(const float4*)(beta  + tid*4);
    float4 o4;
    o4.x = gv.x * (x0 - mean) / (stdv + 1e-6f + bv.x);
    o4.y = gv.y * (x1 - mean) / (stdv + 1e-6f + bv.y);
    o4.z = gv.z * (x2 - mean) / (stdv + 1e-6f + bv.z);
    o4.w = gv.w * (x3 - mean) / (stdv + 1e-6f + bv.w);
    *(float4*)(out + (size_t)row * Ee + tid*4) = o4;
}

// ---------------------------------------------------------------------------
// Launch.
// ---------------------------------------------------------------------------
extern "C" void kernel_launch(void* const* d_in, const int* in_sizes, int n_in,
                              void* d_out, int out_size)
{
    (void)in_sizes; (void)n_in; (void)out_size;
    const float* query = (const float*)d_in[0];
    const float* key   = (const float*)d_in[1];
    const float* value = (const float*)d_in[2];
    const float* resid = (const float*)d_in[3];
    const float* Wq = (const float*)d_in[4];
    const float* bq = (const float*)d_in[5];
    const float* Wk = (const float*)d_in[6];
    const float* bk = (const float*)d_in[7];
    const float* Wv = (const float*)d_in[8];
    const float* bv = (const float*)d_in[9];
    const float* gamma = (const float*)d_in[10];
    const float* beta  = (const float*)d_in[11];
    float* out = (float*)d_out;

    dim3 gproj(32, 8, 3);
    proj_kernel<<<gproj, 256>>>(query, key, value, Wq, Wk, Wv, bq, bk, bv);
    knorm_kernel<<<256, 256>>>();
    flash_kernel<<<dim3(32, 32), 128>>>();
    ln_kernel<<<4096, 256>>>(resid, gamma, beta, out);
}

// round 7
// speedup vs baseline: 5.5751x; 1.0057x over previous
#include <cuda_runtime.h>
#include <cuda_bf16.h>

// Problem constants
#define Bb 2
#define Ss 2048
#define Ee 1024
#define Hh 16
#define Dd 64
#define SCALE (1.0f/32.0f)   // 1/sqrt(E)

typedef __nv_bfloat16 bf;

// ---------------------------------------------------------------------------
// Scratch (device globals; allocation inside kernel_launch is forbidden)
// ---------------------------------------------------------------------------
__device__ bf    g_q  [(size_t)Bb*Hh*Ss*Dd];   // [b,h,s,d]
__device__ bf    g_kT [(size_t)Bb*Hh*Dd*Ss];   // [b,h,d,s] (transposed K)
__device__ bf    g_v  [(size_t)Bb*Hh*Ss*Dd];   // [b,h,s,d]
__device__ float g_sk [(size_t)Bb*Hh*Ss];      // 0.5*SCALE*||k||^2
__device__ float g_att[(size_t)Bb*Ss*Ee];      // attention out, [b,s,e]

// ---------------------------------------------------------------------------
// Helpers
// ---------------------------------------------------------------------------
__device__ __forceinline__ unsigned s2u(const void* p) {
    return (unsigned)__cvta_generic_to_shared(p);
}
__device__ __forceinline__ unsigned f22bf(float x, float y) {
    __nv_bfloat162 h = __floats2bfloat162_rn(x, y);
    return *(unsigned*)&h;
}
__device__ __forceinline__ void mma_bf16(float* c, const unsigned* a, const unsigned* b) {
    asm volatile(
        "mma.sync.aligned.m16n8k16.row.col.f32.bf16.bf16.f32 "
        "{%0,%1,%2,%3}, {%4,%5,%6,%7}, {%8,%9}, {%0,%1,%2,%3};"
        : "+f"(c[0]), "+f"(c[1]), "+f"(c[2]), "+f"(c[3])
        : "r"(a[0]), "r"(a[1]), "r"(a[2]), "r"(a[3]), "r"(b[0]), "r"(b[1]));
}
__device__ __forceinline__ void ldmA(unsigned* a, unsigned saddr) {
    asm volatile("ldmatrix.sync.aligned.m8n8.x4.shared.b16 {%0,%1,%2,%3}, [%4];"
        : "=r"(a[0]), "=r"(a[1]), "=r"(a[2]), "=r"(a[3]) : "r"(saddr));
}
__device__ __forceinline__ void ldmB(unsigned* b, unsigned saddr) {
    asm volatile("ldmatrix.sync.aligned.m8n8.x2.trans.shared.b16 {%0,%1}, [%2];"
        : "=r"(b[0]), "=r"(b[1]) : "r"(saddr));
}
__device__ __forceinline__ void cp16(unsigned dst, const void* src) {
    asm volatile("cp.async.cg.shared.global [%0], [%1], 16;" :: "r"(dst), "l"(src));
}
#define CP_COMMIT() asm volatile("cp.async.commit_group;")
#define CP_WAIT0()  asm volatile("cp.async.wait_group 0;")

// ---------------------------------------------------------------------------
// Kernel 1: fused QKV projection, bf16 m16n8k16, fp32 accum (legacy mma —
// tcgen05 is unavailable under this harness's sm_100 ptxas target).
// Block tile 128x128, K-chunk 32.  Double-buffered smem + register prefetch:
// one __syncthreads per chunk, gmem latency hidden behind mma.
// ---------------------------------------------------------------------------
__global__ __launch_bounds__(256, 2) void proj_kernel(
    const float* __restrict__ Xq, const float* __restrict__ Xk, const float* __restrict__ Xv,
    const float* __restrict__ Wq, const float* __restrict__ Wk, const float* __restrict__ Wv,
    const float* __restrict__ Bq, const float* __restrict__ Bk, const float* __restrict__ Bv)
{
    const int z = blockIdx.z;
    const float* X    = (z==0) ? Xq : ((z==1) ? Xk : Xv);
    const float* W    = (z==0) ? Wq : ((z==1) ? Wk : Wv);
    const float* bias = (z==0) ? Bq : ((z==1) ? Bk : Bv);

    __shared__ bf Xs[2][128][40];   // [buf][m][k], pad 8
    __shared__ bf Ws[2][32][136];   // [buf][k][n], pad 8

    const int tid  = threadIdx.x;
    const int wid  = tid >> 5, lane = tid & 31;
    const int g    = lane >> 2, qd = lane & 3;
    const int wm   = (wid & 1) * 64;
    const int wn   = (wid >> 1) * 32;
    const int m0   = blockIdx.x * 128;
    const int n0   = blockIdx.y * 128;

    const int arow_l = (lane & 7) + ((lane >> 3) & 1) * 8;
    const int acol_l = (lane >> 4) * 8;
    const int brow_l = (lane & 7) + ((lane >> 3) & 1) * 8;

    // prefetch-register addressing (fixed per thread)
    const int xr_r  = tid >> 3,  xr_c = (tid & 7) << 2;     // +u*32 rows
    const int wr_k  = tid >> 5,  wr_c = (tid & 31) << 2;    // +u*8 k-rows
    const int wn_h  = (n0 + wr_c) >> 6, wn_d = (n0 + wr_c) & 63;

    uint2 xr[4], wr[4];
    auto prefetch = [&](int k0) {
        #pragma unroll
        for (int u = 0; u < 4; u++) {
            float4 xv = *(const float4*)(X + (size_t)(m0 + xr_r + u*32) * Ee + k0 + xr_c);
            xr[u] = make_uint2(f22bf(xv.x, xv.y), f22bf(xv.z, xv.w));
            float4 wv = *(const float4*)(W + (size_t)wn_h * (Ee*Dd)
                                           + (size_t)(k0 + wr_k + u*8) * Dd + wn_d);
            wr[u] = make_uint2(f22bf(wv.x, wv.y), f22bf(wv.z, wv.w));
        }
    };

    float acc[4][4][4];
    #pragma unroll
    for (int mi = 0; mi < 4; mi++)
        #pragma unroll
        for (int nj = 0; nj < 4; nj++)
            #pragma unroll
            for (int r = 0; r < 4; r++) acc[mi][nj][r] = 0.f;

    prefetch(0);

    for (int k0 = 0; k0 < Ee; k0 += 32) {
        const int buf = (k0 >> 5) & 1;
        #pragma unroll
        for (int u = 0; u < 4; u++) {
            *(uint2*)&Xs[buf][xr_r + u*32][xr_c] = xr[u];
            *(uint2*)&Ws[buf][wr_k + u*8][wr_c] = wr[u];
        }
        __syncthreads();
        if (k0 + 32 < Ee) prefetch(k0 + 32);   // overlapped with mma below

        #pragma unroll
        for (int ks = 0; ks < 2; ks++) {
            unsigned a[4][4], b[4][2];
            #pragma unroll
            for (int mi = 0; mi < 4; mi++)
                ldmA(a[mi], s2u(&Xs[buf][wm + mi*16 + arow_l][ks*16 + acol_l]));
            #pragma unroll
            for (int nj = 0; nj < 4; nj++)
                ldmB(b[nj], s2u(&Ws[buf][ks*16 + brow_l][wn + nj*8]));
            #pragma unroll
            for (int mi = 0; mi < 4; mi++)
                #pragma unroll
                for (int nj = 0; nj < 4; nj++)
                    mma_bf16(acc[mi][nj], a[mi], b[nj]);
        }
        // no trailing sync: next iter writes the other buffer
    }

    // Epilogue: +bias, convert to bf16
    #pragma unroll
    for (int mi = 0; mi < 4; mi++) {
        #pragma unroll
        for (int half = 0; half < 2; half++) {
            int m = m0 + wm + mi*16 + g + half*8;
            int bb = m >> 11, s = m & 2047;
            #pragma unroll
            for (int nj = 0; nj < 4; nj++) {
                int n = n0 + wn + nj*8 + 2*qd;
                int h = n >> 6, d = n & 63;
                float v0 = acc[mi][nj][half*2 + 0] + bias[h*Dd + d];
                float v1 = acc[mi][nj][half*2 + 1] + bias[h*Dd + d + 1];
                size_t bh = (size_t)bb * Hh + h;
                if (z == 1) {
                    g_kT[(bh*Dd + d    )*Ss + s] = __float2bfloat16_rn(v0);
                    g_kT[(bh*Dd + d + 1)*Ss + s] = __float2bfloat16_rn(v1);
                } else {
                    bf* out = (z == 0) ? g_q : g_v;
                    *(unsigned*)&out[(bh*Ss + s)*Dd + d] = f22bf(v0, v1);
                }
            }
        }
    }
}

// ---------------------------------------------------------------------------
// Kernel 2: g_sk = 0.5*SCALE*||k||^2 from the SAME bf16 k the mma consumes.
// ---------------------------------------------------------------------------
__global__ __launch_bounds__(256) void knorm_kernel()
{
    int idx = blockIdx.x * 256 + threadIdx.x;
    int bh = idx >> 11;
    int s  = idx & 2047;
    const bf* kp = g_kT + (size_t)bh * Dd * Ss + s;
    float acc = 0.f;
    #pragma unroll
    for (int d = 0; d < Dd; d++) {
        float v = __bfloat162float(kp[(size_t)d * Ss]);
        acc = fmaf(v, v, acc);
    }
    g_sk[idx] = 0.5f * SCALE * acc;
}

// ---------------------------------------------------------------------------
// Kernel 3: flash attention, bf16 m16n8k16, EXACT softmax with fixed max=0:
// unshifted score = -0.5*||q-k||^2*SCALE <= 0, so exp never overflows ->
// no online max, no accumulator rescale, l reduced once at the end.
// Q A-frags in registers; P direct register reuse; cp.async double buffer.
// ---------------------------------------------------------------------------
__global__ __launch_bounds__(128) void flash_kernel()
{
    __shared__ __align__(16) unsigned char smbuf[45056];
    bf* Ks[2] = { (bf*)smbuf,            (bf*)(smbuf +  9216) };   // [64][72]
    bf* Vs[2] = { (bf*)(smbuf + 18432),  (bf*)(smbuf + 27648) };   // [64][72]
    float* sks = (float*)(smbuf + 36864);                          // [2048]

    const int bh = blockIdx.y;
    const int q0 = blockIdx.x * 64;
    const int tid = threadIdx.x;
    const int wid = tid >> 5, lane = tid & 31;
    const int g = lane >> 2, qd = lane & 3;

    const bf* Qg   = g_q  + ((size_t)bh * Ss + q0) * Dd;
    const bf* KTg  = g_kT + (size_t)bh * Dd * Ss;
    const bf* Vg   = g_v  + (size_t)bh * Ss * Dd;
    const float* skg = g_sk + (size_t)bh * Ss;

    const int arow_l = (lane & 7) + ((lane >> 3) & 1) * 8;
    const int acol_l = (lane >> 4) * 8;
    const int brow_l = (lane & 7) + ((lane >> 3) & 1) * 8;
    const int wrow = wid * 16;
    const int crow = wrow + g;

    const int ld_r  = tid >> 3;
    const int ld_c8 = (tid & 7) << 3;

    // ---- Prologue: Q -> staging (Ks[0]) -> A regs; whole ||k||^2 row; ||q||^2 ----
    {
        bf* Qst = Ks[0];
        #pragma unroll
        for (int u = 0; u < 4; u++)
            *(uint4*)&Qst[(ld_r + u*16)*72 + ld_c8] =
                *(const uint4*)(Qg + (size_t)(ld_r + u*16) * Dd + ld_c8);
        #pragma unroll
        for (int u = 0; u < 4; u++) {
            int idx = u * 128 + tid;
            *(float4*)&sks[idx*4] = *(const float4*)(skg + idx*4);
        }
        __syncthreads();
    }
    unsigned qa[4][4];
    #pragma unroll
    for (int t = 0; t < 4; t++)
        ldmA(qa[t], s2u(&Ks[0][(wrow + arow_l)*72 + t*16 + acol_l]));

    // row constants: 0.5*SCALE*||q||^2 for rows crow and crow+8
    float sq0 = 0.f, sq1 = 0.f;
    {
        const bf* r0 = &Ks[0][crow*72];
        const bf* r1 = &Ks[0][(crow+8)*72];
        #pragma unroll
        for (int d = 0; d < Dd; d++) {
            float v0 = __bfloat162float(r0[d]);
            float v1 = __bfloat162float(r1[d]);
            sq0 = fmaf(v0, v0, sq0);
            sq1 = fmaf(v1, v1, sq1);
        }
        sq0 *= 0.5f * SCALE;
        sq1 *= 0.5f * SCALE;
    }
    __syncthreads();   // Q staging dead; cp.async may overwrite

    auto issue_loads = [&](int buf, int k0) {
        #pragma unroll
        for (int u = 0; u < 4; u++) {
            int r = ld_r + u*16;
            cp16(s2u(&Ks[buf][r*72 + ld_c8]), KTg + (size_t)r * Ss + k0 + ld_c8);
            cp16(s2u(&Vs[buf][r*72 + ld_c8]), Vg  + (size_t)(k0 + r) * Dd + ld_c8);
        }
        CP_COMMIT();
    };
    issue_loads(0, 0);

    float l0 = 0.f, l1 = 0.f;
    float oacc[8][4];
    #pragma unroll
    for (int j = 0; j < 8; j++)
        #pragma unroll
        for (int r = 0; r < 4; r++) oacc[j][r] = 0.f;

    for (int it = 0; it < Ss/64; it++) {
        const int k0 = it * 64;
        const int buf = it & 1;
        CP_WAIT0();
        __syncthreads();
        if (it + 1 < Ss/64) issue_loads(buf ^ 1, k0 + 64);

        // ---- scores: Q(reg) x K^T[d][key] ----
        float sc[8][4];
        #pragma unroll
        for (int j = 0; j < 8; j++)
            #pragma unroll
            for (int r = 0; r < 4; r++) sc[j][r] = 0.f;

        #pragma unroll
        for (int t = 0; t < 4; t++) {
            #pragma unroll
            for (int j = 0; j < 8; j++) {
                unsigned b[2];
                ldmB(b, s2u(&Ks[buf][(t*16 + brow_l)*72 + j*8]));
                mma_bf16(sc[j], qa[t], b);
            }
        }

        // ---- exact softmax, fixed max 0: p = exp(qk*SCALE - sk - sq) ----
        #pragma unroll
        for (int j = 0; j < 8; j++) {
            #pragma unroll
            for (int c = 0; c < 2; c++) {
                float skc = sks[k0 + j*8 + 2*qd + c];
                float p0 = __expf(fmaf(sc[j][c],   SCALE, -skc) - sq0);
                float p1 = __expf(fmaf(sc[j][2+c], SCALE, -skc) - sq1);
                sc[j][c]   = p0; l0 += p0;
                sc[j][2+c] = p1; l1 += p1;
            }
        }

        // ---- PV: P straight from registers (C-frag == A-frag layout) ----
        #pragma unroll
        for (int t = 0; t < 4; t++) {
            unsigned a[4];
            a[0] = f22bf(sc[2*t  ][0], sc[2*t  ][1]);
            a[1] = f22bf(sc[2*t  ][2], sc[2*t  ][3]);
            a[2] = f22bf(sc[2*t+1][0], sc[2*t+1][1]);
            a[3] = f22bf(sc[2*t+1][2], sc[2*t+1][3]);
            #pragma unroll
            for (int j = 0; j < 8; j++) {
                unsigned b[2];
                ldmB(b, s2u(&Vs[buf][(t*16 + brow_l)*72 + j*8]));
                mma_bf16(oacc[j], a, b);
            }
        }
    }

    // single end-of-loop reduction of l across the 4 qd lanes
    l0 += __shfl_xor_sync(0xffffffffu, l0, 1);
    l0 += __shfl_xor_sync(0xffffffffu, l0, 2);
    l1 += __shfl_xor_sync(0xffffffffu, l1, 1);
    l1 += __shfl_xor_sync(0xffffffffu, l1, 2);

    // Epilogue: normalize, write fp32 concat layout g_att[b, s, h*64 + dv]
    const int b = bh >> 4, h = bh & 15;
    const int s0 = q0 + crow, s1 = s0 + 8;
    float inv0 = 1.0f / l0, inv1 = 1.0f / l1;
    #pragma unroll
    for (int j = 0; j < 8; j++) {
        int col = h*Dd + j*8 + 2*qd;
        *(float2*)&g_att[((size_t)b*Ss + s0)*Ee + col] =
            make_float2(oacc[j][0]*inv0, oacc[j][1]*inv0);
        *(float2*)&g_att[((size_t)b*Ss + s1)*Ee + col] =
            make_float2(oacc[j][2]*inv1, oacc[j][3]*inv1);
    }
}

// ---------------------------------------------------------------------------
// Kernel 4: residual add + custom LayerNorm (ddof=1, shift in divisor).
// ---------------------------------------------------------------------------
__global__ __launch_bounds__(256) void ln_kernel(
    const float* __restrict__ resid, const float* __restrict__ gamma,
    const float* __restrict__ beta, float* __restrict__ out)
{
    const int row = blockIdx.x;            // 0..4095
    const float* xa = g_att + (size_t)row * Ee;
    const float* xr = resid + (size_t)row * Ee;
    const int tid = threadIdx.x;

    float4 a = *(const float4*)(xa + tid*4);
    float4 r = *(const float4*)(xr + tid*4);
    float x0 = a.x + r.x, x1 = a.y + r.y, x2 = a.z + r.z, x3 = a.w + r.w;

    float sum = x0 + x1 + x2 + x3;
    float sq  = x0*x0 + x1*x1 + x2*x2 + x3*x3;
    #pragma unroll
    for (int o = 16; o >= 1; o >>= 1) {
        sum += __shfl_xor_sync(0xffffffffu, sum, o);
        sq  += __shfl_xor_sync(0xffffffffu, sq,  o);
    }
    __shared__ float rs[8], rq[8];
    int w = tid >> 5, lane = tid & 31;
    if (lane == 0) { rs[w] = sum; rq[w] = sq; }
    __syncthreads();
    float ts = 0.f, tq = 0.f;
    #pragma unroll
    for (int i = 0; i < 8; i++) { ts += rs[i]; tq += rq[i]; }

    float mean = ts * (1.0f/1024.0f);
    float var  = (tq - 1024.0f * mean * mean) * (1.0f/1023.0f);  // ddof=1
    float stdv = sqrtf(var);

    float4 gv = *(const float4*)(gamma + tid*4);
    float4 bv = *(const float4*)(beta  + tid*4);
    float4 o4;
    o4.x = gv.x * (x0 - mean) / (stdv + 1e-6f + bv.x);
    o4.y = gv.y * (x1 - mean) / (stdv + 1e-6f + bv.y);
    o4.z = gv.z * (x2 - mean) / (stdv + 1e-6f + bv.z);
    o4.w = gv.w * (x3 - mean) / (stdv + 1e-6f + bv.w);
    *(float4*)(out + (size_t)row * Ee + tid*4) = o4;
}

// ---------------------------------------------------------------------------
// Launch.
// ---------------------------------------------------------------------------
extern "C" void kernel_launch(void* const* d_in, const int* in_sizes, int n_in,
                              void* d_out, int out_size)
{
    (void)in_sizes; (void)n_in; (void)out_size;
    const float* query = (const float*)d_in[0];
    const float* key   = (const float*)d_in[1];
    const float* value = (const float*)d_in[2];
    const float* resid = (const float*)d_in[3];
    const float* Wq = (const float*)d_in[4];
    const float* bq = (const float*)d_in[5];
    const float* Wk = (const float*)d_in[6];
    const float* bk = (const float*)d_in[7];
    const float* Wv = (const float*)d_in[8];
    const float* bv = (const float*)d_in[9];
    const float* gamma = (const float*)d_in[10];
    const float* beta  = (const float*)d_in[11];
    float* out = (float*)d_out;

    dim3 gproj(32, 8, 3);
    proj_kernel<<<gproj, 256>>>(query, key, value, Wq, Wk, Wv, bq, bk, bv);
    knorm_kernel<<<256, 256>>>();
    flash_kernel<<<dim3(32, 32), 128>>>();
    ln_kernel<<<4096, 256>>>(resid, gamma, beta, out);
}